// round 1
// baseline (speedup 1.0000x reference)
#include <cuda_runtime.h>
#include <cuda_bf16.h>
#include <cstdint>

// Problem shapes (fixed per reference)
#define B_  4
#define T_  64
#define L_  128
#define D_  768
#define H_  12
#define HD_ 64   // head dim

// -------------------- scratch (device globals; no allocation) --------------------
__device__ float g_Wkv[2 * D_ * D_];              // [1536, 768]  concat(Wk, Wv)
__device__ float g_kvproj[B_ * T_ * 2 * D_];      // [256, 1536]  rows=(b,t), cols: [0,768)=k, [768,1536)=v
__device__ float g_M[(size_t)B_ * T_ * H_ * HD_ * HD_]; // [B,T,H,64,64]
__device__ float g_q[(size_t)B_ * T_ * L_ * D_];  // [32768, 768]

// -------------------- kernel 0: concat Wk,Wv --------------------
__global__ void concat_w_kernel(const float* __restrict__ Wk, const float* __restrict__ Wv) {
    int i = blockIdx.x * blockDim.x + threadIdx.x;
    if (i < D_ * D_) {
        g_Wkv[i] = Wk[i];
        g_Wkv[D_ * D_ + i] = Wv[i];
    }
}

// -------------------- generic NT SGEMM: C[M,N] = A[M,K] @ B[N,K]^T --------------------
// Both A and B row-major with K contiguous. Dims must divide block tiles.
template <int BM, int BN, int BK, int TM, int TN>
__global__ void sgemm_nt_kernel(const float* __restrict__ A, const float* __restrict__ Bm,
                                float* __restrict__ C, int M, int N, int K) {
    constexpr int THREADS = (BM / TM) * (BN / TN);   // 256 in both instantiations
    __shared__ float As[BK][BM + 4];
    __shared__ float Bs[BK][BN + 4];

    const int tid = threadIdx.x;
    const int tx  = tid % (BN / TN);
    const int ty  = tid / (BN / TN);
    const int row0 = blockIdx.y * BM;
    const int col0 = blockIdx.x * BN;

    float acc[TM][TN];
#pragma unroll
    for (int i = 0; i < TM; i++)
#pragma unroll
        for (int j = 0; j < TN; j++) acc[i][j] = 0.0f;

    constexpr int A_LD = (BM * BK) / (4 * THREADS); // float4 loads per thread
    constexpr int B_LD = (BN * BK) / (4 * THREADS);

    for (int k0 = 0; k0 < K; k0 += BK) {
#pragma unroll
        for (int i = 0; i < A_LD; i++) {
            int idx = tid + i * THREADS;           // over BM*BK/4 float4 slots
            int r   = idx / (BK / 4);
            int kq  = idx % (BK / 4);
            float4 v = *reinterpret_cast<const float4*>(
                &A[(size_t)(row0 + r) * K + k0 + kq * 4]);
            As[kq * 4 + 0][r] = v.x;
            As[kq * 4 + 1][r] = v.y;
            As[kq * 4 + 2][r] = v.z;
            As[kq * 4 + 3][r] = v.w;
        }
#pragma unroll
        for (int i = 0; i < B_LD; i++) {
            int idx = tid + i * THREADS;
            int r   = idx / (BK / 4);
            int kq  = idx % (BK / 4);
            float4 v = *reinterpret_cast<const float4*>(
                &Bm[(size_t)(col0 + r) * K + k0 + kq * 4]);
            Bs[kq * 4 + 0][r] = v.x;
            Bs[kq * 4 + 1][r] = v.y;
            Bs[kq * 4 + 2][r] = v.z;
            Bs[kq * 4 + 3][r] = v.w;
        }
        __syncthreads();

#pragma unroll
        for (int kk = 0; kk < BK; kk++) {
            float ar[TM], br[TN];
#pragma unroll
            for (int i = 0; i < TM; i++) ar[i] = As[kk][ty * TM + i];
#pragma unroll
            for (int j = 0; j < TN; j++) br[j] = Bs[kk][tx * TN + j];
#pragma unroll
            for (int i = 0; i < TM; i++)
#pragma unroll
                for (int j = 0; j < TN; j++) acc[i][j] += ar[i] * br[j];
        }
        __syncthreads();
    }

#pragma unroll
    for (int i = 0; i < TM; i++) {
#pragma unroll
        for (int j = 0; j < TN; j += 4) {
            float4 v = make_float4(acc[i][j], acc[i][j + 1], acc[i][j + 2], acc[i][j + 3]);
            *reinterpret_cast<float4*>(
                &C[(size_t)(row0 + ty * TM + i) * N + col0 + tx * TN + j]) = v;
        }
    }
}

// -------------------- kernel 2: speaker-segmented prefix sum of outer products --------------------
// M[b,t,h,d,e] = sum_{u<=t, spk[u]==spk[t]} k[b,u,h,d]*v[b,u,h,e]
// grid (T, H, B), 128 threads. Thread: d = tid>>1, e-range = (tid&1)*32 .. +32.
__global__ void compute_M_kernel(const int* __restrict__ spk) {
    const int t = blockIdx.x, h = blockIdx.y, b = blockIdx.z;
    const int tid = threadIdx.x;

    __shared__ float ks[HD_];
    __shared__ float vs[HD_];
    __shared__ int sspk[T_];

    if (tid < T_) sspk[tid] = spk[b * T_ + tid];
    __syncthreads();
    const int myspk = sspk[t];

    const int d  = tid >> 1;
    const int e0 = (tid & 1) * 32;

    float acc[32];
#pragma unroll
    for (int e = 0; e < 32; e++) acc[e] = 0.0f;

    const float* base = g_kvproj + (size_t)(b * T_) * (2 * D_);

    for (int u = 0; u <= t; u++) {
        if (sspk[u] != myspk) continue;   // uniform across block
        __syncthreads();
        if (tid < 64)
            ks[tid] = base[(size_t)u * (2 * D_) + h * HD_ + tid];
        else
            vs[tid - 64] = base[(size_t)u * (2 * D_) + D_ + h * HD_ + (tid - 64)];
        __syncthreads();
        float kd = ks[d];
#pragma unroll
        for (int e = 0; e < 32; e++) acc[e] += kd * vs[e0 + e];
    }

    float* out = g_M + ((size_t)((b * T_ + t) * H_ + h)) * (HD_ * HD_) + d * HD_ + e0;
#pragma unroll
    for (int e = 0; e < 32; e += 4) {
        *reinterpret_cast<float4*>(&out[e]) =
            make_float4(acc[e], acc[e + 1], acc[e + 2], acc[e + 3]);
    }
}

// -------------------- kernel 4: out = x + q @ M (per b,t,h) --------------------
// grid (H, T, B), 256 threads. Thread: token l = tid>>1, e-range = (tid&1)*32 .. +32.
__global__ void attn_out_kernel(const float* __restrict__ x, float* __restrict__ out) {
    const int h = blockIdx.x, t = blockIdx.y, b = blockIdx.z;
    const int tid = threadIdx.x;

    __shared__ float Ms[HD_][HD_];

    const float* Mg = g_M + ((size_t)((b * T_ + t) * H_ + h)) * (HD_ * HD_);
#pragma unroll
    for (int i = 0; i < 4; i++) {
        int idx = tid + i * 256;   // 1024 float4 = 4096 floats
        reinterpret_cast<float4*>(&Ms[0][0])[idx] =
            reinterpret_cast<const float4*>(Mg)[idx];
    }
    __syncthreads();

    const int l  = tid >> 1;
    const int e0 = (tid & 1) * 32;

    const size_t rowbase = ((size_t)((b * T_ + t) * L_ + l)) * D_ + h * HD_;

    float qreg[HD_];
#pragma unroll
    for (int i = 0; i < HD_ / 4; i++) {
        float4 v = reinterpret_cast<const float4*>(&g_q[rowbase])[i];
        qreg[4 * i + 0] = v.x;
        qreg[4 * i + 1] = v.y;
        qreg[4 * i + 2] = v.z;
        qreg[4 * i + 3] = v.w;
    }

    float acc[32];
#pragma unroll
    for (int e = 0; e < 32; e++) acc[e] = 0.0f;

#pragma unroll
    for (int d = 0; d < HD_; d++) {
        float qd = qreg[d];
#pragma unroll
        for (int e = 0; e < 32; e++) acc[e] += qd * Ms[d][e0 + e];
    }

    const float* xrow = x + rowbase + e0;
    float* orow = out + rowbase + e0;
#pragma unroll
    for (int e = 0; e < 32; e += 4) {
        float4 xv = *reinterpret_cast<const float4*>(&xrow[e]);
        *reinterpret_cast<float4*>(&orow[e]) =
            make_float4(acc[e] + xv.x, acc[e + 1] + xv.y,
                        acc[e + 2] + xv.z, acc[e + 3] + xv.w);
    }
}

// -------------------- launch --------------------
extern "C" void kernel_launch(void* const* d_in, const int* in_sizes, int n_in,
                              void* d_out, int out_size) {
    // inputs (metadata order): input_ids(i32, unused), speaker_ids(i32),
    // token_embeddings(f32), edu_embeddings(f32), Wk, Wv, Wq (f32)
    const int*   spk = (const int*)d_in[1];
    const float* tok = (const float*)d_in[2];
    const float* edu = (const float*)d_in[3];
    const float* Wk  = (const float*)d_in[4];
    const float* Wv  = (const float*)d_in[5];
    const float* Wq  = (const float*)d_in[6];
    float* out = (float*)d_out;

    float* p_Wkv;    cudaGetSymbolAddress((void**)&p_Wkv,    g_Wkv);
    float* p_kvproj; cudaGetSymbolAddress((void**)&p_kvproj, g_kvproj);
    float* p_q;      cudaGetSymbolAddress((void**)&p_q,      g_q);

    // 0) concat Wk,Wv
    concat_w_kernel<<<(D_ * D_ + 255) / 256, 256>>>(Wk, Wv);

    // 1) kv projection: [256,1536] = edu[256,768] @ Wkv[1536,768]^T
    {
        dim3 grid((2 * D_) / 64, (B_ * T_) / 64);
        sgemm_nt_kernel<64, 64, 16, 4, 4><<<grid, 256>>>(edu, p_Wkv, p_kvproj,
                                                         B_ * T_, 2 * D_, D_);
    }

    // 2) speaker-segmented memory matrices M
    {
        dim3 grid(T_, H_, B_);
        compute_M_kernel<<<grid, 128>>>(spk);
    }

    // 3) q projection: [32768,768] = tok[32768,768] @ Wq[768,768]^T   (dominant GEMM)
    {
        dim3 grid(D_ / 128, (B_ * T_ * L_) / 128);
        sgemm_nt_kernel<128, 128, 16, 8, 8><<<grid, 256>>>(tok, Wq, p_q,
                                                           B_ * T_ * L_, D_, D_);
    }

    // 4) out = tok + q @ M
    {
        dim3 grid(H_, T_, B_);
        attn_out_kernel<<<grid, 256>>>(tok, out);
    }
}

// round 3
// speedup vs baseline: 1.6510x; 1.6510x over previous
#include <cuda_runtime.h>
#include <cuda_bf16.h>
#include <cstdint>

// Problem shapes (fixed per reference)
#define B_  4
#define T_  64
#define L_  128
#define D_  768
#define H_  12
#define HD_ 64   // head dim

// -------------------- scratch (device globals; no allocation) --------------------
__device__ float g_Wkv[2 * D_ * D_];              // [1536, 768]  concat(Wk, Wv)
__device__ float g_kvproj[B_ * T_ * 2 * D_];      // [256, 1536]  rows=(b,t), cols: [0,768)=k, [768,1536)=v
__device__ float g_M[(size_t)B_ * T_ * H_ * HD_ * HD_]; // [B,T,H,64,64]
__device__ float g_q[(size_t)B_ * T_ * L_ * D_];  // [32768, 768]

// -------------------- kernel 0: concat Wk,Wv --------------------
__global__ void concat_w_kernel(const float* __restrict__ Wk, const float* __restrict__ Wv) {
    int i = blockIdx.x * blockDim.x + threadIdx.x;
    if (i < D_ * D_) {
        g_Wkv[i] = Wk[i];
        g_Wkv[D_ * D_ + i] = Wv[i];
    }
}

// -------------------- generic NT SGEMM (fp32, for small kv projection) --------------------
template <int BM, int BN, int BK, int TM, int TN>
__global__ void sgemm_nt_kernel(const float* __restrict__ A, const float* __restrict__ Bm,
                                float* __restrict__ C, int M, int N, int K) {
    constexpr int THREADS = (BM / TM) * (BN / TN);
    __shared__ float As[BK][BM + 4];
    __shared__ float Bs[BK][BN + 4];

    const int tid = threadIdx.x;
    const int tx  = tid % (BN / TN);
    const int ty  = tid / (BN / TN);
    const int row0 = blockIdx.y * BM;
    const int col0 = blockIdx.x * BN;

    float acc[TM][TN];
#pragma unroll
    for (int i = 0; i < TM; i++)
#pragma unroll
        for (int j = 0; j < TN; j++) acc[i][j] = 0.0f;

    constexpr int A_LD = (BM * BK) / (4 * THREADS);
    constexpr int B_LD = (BN * BK) / (4 * THREADS);

    for (int k0 = 0; k0 < K; k0 += BK) {
#pragma unroll
        for (int i = 0; i < A_LD; i++) {
            int idx = tid + i * THREADS;
            int r   = idx / (BK / 4);
            int kq  = idx % (BK / 4);
            float4 v = *reinterpret_cast<const float4*>(
                &A[(size_t)(row0 + r) * K + k0 + kq * 4]);
            As[kq * 4 + 0][r] = v.x;
            As[kq * 4 + 1][r] = v.y;
            As[kq * 4 + 2][r] = v.z;
            As[kq * 4 + 3][r] = v.w;
        }
#pragma unroll
        for (int i = 0; i < B_LD; i++) {
            int idx = tid + i * THREADS;
            int r   = idx / (BK / 4);
            int kq  = idx % (BK / 4);
            float4 v = *reinterpret_cast<const float4*>(
                &Bm[(size_t)(col0 + r) * K + k0 + kq * 4]);
            Bs[kq * 4 + 0][r] = v.x;
            Bs[kq * 4 + 1][r] = v.y;
            Bs[kq * 4 + 2][r] = v.z;
            Bs[kq * 4 + 3][r] = v.w;
        }
        __syncthreads();

#pragma unroll
        for (int kk = 0; kk < BK; kk++) {
            float ar[TM], br[TN];
#pragma unroll
            for (int i = 0; i < TM; i++) ar[i] = As[kk][ty * TM + i];
#pragma unroll
            for (int j = 0; j < TN; j++) br[j] = Bs[kk][tx * TN + j];
#pragma unroll
            for (int i = 0; i < TM; i++)
#pragma unroll
                for (int j = 0; j < TN; j++) acc[i][j] += ar[i] * br[j];
        }
        __syncthreads();
    }

#pragma unroll
    for (int i = 0; i < TM; i++) {
#pragma unroll
        for (int j = 0; j < TN; j += 4) {
            float4 v = make_float4(acc[i][j], acc[i][j + 1], acc[i][j + 2], acc[i][j + 3]);
            *reinterpret_cast<float4*>(
                &C[(size_t)(row0 + ty * TM + i) * N + col0 + tx * TN + j]) = v;
        }
    }
}

// -------------------- TF32 tensor-core GEMM: C[M,N] = A[M,K] @ B[N,K]^T --------------------
// Tiles: BM=128, BN=64, BK=32. 256 threads = 8 warps (4 m x 2 n), warp tile 32x32.
// mma.sync.m16n8k8.tf32: per warp 2 m-tiles x 4 n-tiles x 4 k-steps per BK.
// SMEM holds TF32 (rna-rounded) in permuted-k layout: perm(c) = (c%4)*8 + c/4,
// row stride 44 floats -> conflict-free 128-bit fragment loads.

#define QBM 128
#define QBN 64
#define QBK 32
#define QLD 44   // smem row stride in words

__device__ __forceinline__ uint32_t f32_to_tf32(float x) {
    uint32_t r;
    asm volatile("cvt.rna.tf32.f32 %0, %1;" : "=r"(r) : "f"(x));
    return r;
}

__device__ __forceinline__ void mma_tf32(float c[4], uint32_t a0, uint32_t a1,
                                         uint32_t a2, uint32_t a3,
                                         uint32_t b0, uint32_t b1) {
    asm volatile(
        "mma.sync.aligned.m16n8k8.row.col.f32.tf32.tf32.f32 "
        "{%0,%1,%2,%3}, {%4,%5,%6,%7}, {%8,%9}, {%0,%1,%2,%3};"
        : "+f"(c[0]), "+f"(c[1]), "+f"(c[2]), "+f"(c[3])
        : "r"(a0), "r"(a1), "r"(a2), "r"(a3), "r"(b0), "r"(b1));
}

__global__ __launch_bounds__(256)
void qgemm_tf32_kernel(const float* __restrict__ A, const float* __restrict__ Bm,
                       float* __restrict__ C, int M, int N, int K) {
    __shared__ uint32_t As[QBM * QLD];
    __shared__ uint32_t Bs[QBN * QLD];

    const int tid  = threadIdx.x;
    const int warp = tid >> 5;
    const int lane = tid & 31;
    const int gid  = lane >> 2;   // group id (0..7)
    const int c4   = lane & 3;    // thread in group

    const int warp_m = warp & 3;  // 0..3  (rows of 32)
    const int warp_n = warp >> 2; // 0..1  (cols of 32)

    const int row0 = blockIdx.y * QBM;
    const int col0 = blockIdx.x * QBN;

    float cacc[2][4][4];
#pragma unroll
    for (int mt = 0; mt < 2; mt++)
#pragma unroll
        for (int nt = 0; nt < 4; nt++)
#pragma unroll
            for (int i = 0; i < 4; i++) cacc[mt][nt][i] = 0.0f;

    for (int k0 = 0; k0 < K; k0 += QBK) {
        // ---- load A tile (128x32): 1024 float4 slots, 4 per thread ----
#pragma unroll
        for (int i = 0; i < 4; i++) {
            int idx = tid + i * 256;
            int r   = idx >> 3;      // row 0..127
            int cq  = idx & 7;       // float4 within row (c = cq*4)
            float4 v = *reinterpret_cast<const float4*>(
                &A[(size_t)(row0 + r) * K + k0 + cq * 4]);
            uint32_t* dst = &As[r * QLD];
            dst[0 * 8 + cq]  = f32_to_tf32(v.x);
            dst[1 * 8 + cq]  = f32_to_tf32(v.y);
            dst[2 * 8 + cq]  = f32_to_tf32(v.z);
            dst[3 * 8 + cq]  = f32_to_tf32(v.w);
        }
        // ---- load B tile (64x32): 512 float4 slots, 2 per thread ----
#pragma unroll
        for (int i = 0; i < 2; i++) {
            int idx = tid + i * 256;
            int r   = idx >> 3;
            int cq  = idx & 7;
            float4 v = *reinterpret_cast<const float4*>(
                &Bm[(size_t)(col0 + r) * K + k0 + cq * 4]);
            uint32_t* dst = &Bs[r * QLD];
            dst[0 * 8 + cq]  = f32_to_tf32(v.x);
            dst[1 * 8 + cq]  = f32_to_tf32(v.y);
            dst[2 * 8 + cq]  = f32_to_tf32(v.z);
            dst[3 * 8 + cq]  = f32_to_tf32(v.w);
        }
        __syncthreads();

        // ---- fragment loads: per thread 8 floats (2x float4) per needed row ----
        uint32_t af[2][2][8];   // [mt][lo/hi][k-perm 0..7]
#pragma unroll
        for (int mt = 0; mt < 2; mt++) {
            int r_lo = warp_m * 32 + mt * 16 + gid;
            const uint32_t* p0 = &As[r_lo * QLD + c4 * 8];
            const uint32_t* p1 = &As[(r_lo + 8) * QLD + c4 * 8];
            *reinterpret_cast<uint4*>(&af[mt][0][0]) = *reinterpret_cast<const uint4*>(p0);
            *reinterpret_cast<uint4*>(&af[mt][0][4]) = *reinterpret_cast<const uint4*>(p0 + 4);
            *reinterpret_cast<uint4*>(&af[mt][1][0]) = *reinterpret_cast<const uint4*>(p1);
            *reinterpret_cast<uint4*>(&af[mt][1][4]) = *reinterpret_cast<const uint4*>(p1 + 4);
        }
        uint32_t bf[4][8];      // [nt][k-perm 0..7]
#pragma unroll
        for (int nt = 0; nt < 4; nt++) {
            int n = warp_n * 32 + nt * 8 + gid;
            const uint32_t* p = &Bs[n * QLD + c4 * 8];
            *reinterpret_cast<uint4*>(&bf[nt][0]) = *reinterpret_cast<const uint4*>(p);
            *reinterpret_cast<uint4*>(&bf[nt][4]) = *reinterpret_cast<const uint4*>(p + 4);
        }

        // ---- 32 mma per warp ----
#pragma unroll
        for (int ks = 0; ks < 4; ks++) {
#pragma unroll
            for (int mt = 0; mt < 2; mt++) {
#pragma unroll
                for (int nt = 0; nt < 4; nt++) {
                    mma_tf32(cacc[mt][nt],
                             af[mt][0][2 * ks], af[mt][1][2 * ks],
                             af[mt][0][2 * ks + 1], af[mt][1][2 * ks + 1],
                             bf[nt][2 * ks], bf[nt][2 * ks + 1]);
                }
            }
        }
        __syncthreads();
    }

    // ---- epilogue: float2 stores ----
#pragma unroll
    for (int mt = 0; mt < 2; mt++) {
#pragma unroll
        for (int nt = 0; nt < 4; nt++) {
            int row = row0 + warp_m * 32 + mt * 16 + gid;
            int col = col0 + warp_n * 32 + nt * 8 + c4 * 2;
            *reinterpret_cast<float2*>(&C[(size_t)row * N + col]) =
                make_float2(cacc[mt][nt][0], cacc[mt][nt][1]);
            *reinterpret_cast<float2*>(&C[(size_t)(row + 8) * N + col]) =
                make_float2(cacc[mt][nt][2], cacc[mt][nt][3]);
        }
    }
}

// -------------------- kernel 2: speaker-segmented prefix sum of outer products --------------------
__global__ void compute_M_kernel(const int* __restrict__ spk) {
    const int t = blockIdx.x, h = blockIdx.y, b = blockIdx.z;
    const int tid = threadIdx.x;

    __shared__ float ks[HD_];
    __shared__ float vs[HD_];
    __shared__ int sspk[T_];

    if (tid < T_) sspk[tid] = spk[b * T_ + tid];
    __syncthreads();
    const int myspk = sspk[t];

    const int d  = tid >> 1;
    const int e0 = (tid & 1) * 32;

    float acc[32];
#pragma unroll
    for (int e = 0; e < 32; e++) acc[e] = 0.0f;

    const float* base = g_kvproj + (size_t)(b * T_) * (2 * D_);

    for (int u = 0; u <= t; u++) {
        if (sspk[u] != myspk) continue;
        __syncthreads();
        if (tid < 64)
            ks[tid] = base[(size_t)u * (2 * D_) + h * HD_ + tid];
        else
            vs[tid - 64] = base[(size_t)u * (2 * D_) + D_ + h * HD_ + (tid - 64)];
        __syncthreads();
        float kd = ks[d];
#pragma unroll
        for (int e = 0; e < 32; e++) acc[e] += kd * vs[e0 + e];
    }

    float* out = g_M + ((size_t)((b * T_ + t) * H_ + h)) * (HD_ * HD_) + d * HD_ + e0;
#pragma unroll
    for (int e = 0; e < 32; e += 4) {
        *reinterpret_cast<float4*>(&out[e]) =
            make_float4(acc[e], acc[e + 1], acc[e + 2], acc[e + 3]);
    }
}

// -------------------- kernel 4: out = x + q @ M (per b,t,h) --------------------
__global__ void attn_out_kernel(const float* __restrict__ x, float* __restrict__ out) {
    const int h = blockIdx.x, t = blockIdx.y, b = blockIdx.z;
    const int tid = threadIdx.x;

    __shared__ float Ms[HD_][HD_];

    const float* Mg = g_M + ((size_t)((b * T_ + t) * H_ + h)) * (HD_ * HD_);
#pragma unroll
    for (int i = 0; i < 4; i++) {
        int idx = tid + i * 256;
        reinterpret_cast<float4*>(&Ms[0][0])[idx] =
            reinterpret_cast<const float4*>(Mg)[idx];
    }
    __syncthreads();

    const int l  = tid >> 1;
    const int e0 = (tid & 1) * 32;

    const size_t rowbase = ((size_t)((b * T_ + t) * L_ + l)) * D_ + h * HD_;

    float qreg[HD_];
#pragma unroll
    for (int i = 0; i < HD_ / 4; i++) {
        float4 v = reinterpret_cast<const float4*>(&g_q[rowbase])[i];
        qreg[4 * i + 0] = v.x;
        qreg[4 * i + 1] = v.y;
        qreg[4 * i + 2] = v.z;
        qreg[4 * i + 3] = v.w;
    }

    float acc[32];
#pragma unroll
    for (int e = 0; e < 32; e++) acc[e] = 0.0f;

#pragma unroll
    for (int d = 0; d < HD_; d++) {
        float qd = qreg[d];
#pragma unroll
        for (int e = 0; e < 32; e++) acc[e] += qd * Ms[d][e0 + e];
    }

    const float* xrow = x + rowbase + e0;
    float* orow = out + rowbase + e0;
#pragma unroll
    for (int e = 0; e < 32; e += 4) {
        float4 xv = *reinterpret_cast<const float4*>(&xrow[e]);
        *reinterpret_cast<float4*>(&orow[e]) =
            make_float4(acc[e] + xv.x, acc[e + 1] + xv.y,
                        acc[e + 2] + xv.z, acc[e + 3] + xv.w);
    }
}

// -------------------- launch --------------------
extern "C" void kernel_launch(void* const* d_in, const int* in_sizes, int n_in,
                              void* d_out, int out_size) {
    const int*   spk = (const int*)d_in[1];
    const float* tok = (const float*)d_in[2];
    const float* edu = (const float*)d_in[3];
    const float* Wk  = (const float*)d_in[4];
    const float* Wv  = (const float*)d_in[5];
    const float* Wq  = (const float*)d_in[6];
    float* out = (float*)d_out;

    float* p_Wkv;    cudaGetSymbolAddress((void**)&p_Wkv,    g_Wkv);
    float* p_kvproj; cudaGetSymbolAddress((void**)&p_kvproj, g_kvproj);
    float* p_q;      cudaGetSymbolAddress((void**)&p_q,      g_q);

    // 0) concat Wk,Wv
    concat_w_kernel<<<(D_ * D_ + 255) / 256, 256>>>(Wk, Wv);

    // 1) kv projection: [256,1536] = edu[256,768] @ Wkv[1536,768]^T
    {
        dim3 grid((2 * D_) / 64, (B_ * T_) / 64);
        sgemm_nt_kernel<64, 64, 16, 4, 4><<<grid, 256>>>(edu, p_Wkv, p_kvproj,
                                                         B_ * T_, 2 * D_, D_);
    }

    // 2) speaker-segmented memory matrices M
    {
        dim3 grid(T_, H_, B_);
        compute_M_kernel<<<grid, 128>>>(spk);
    }

    // 3) q projection (dominant): TF32 tensor cores
    {
        dim3 grid(D_ / QBN, (B_ * T_ * L_) / QBM);   // (12, 256)
        qgemm_tf32_kernel<<<grid, 256>>>(tok, Wq, p_q, B_ * T_ * L_, D_, D_);
    }

    // 4) out = tok + q @ M
    {
        dim3 grid(H_, T_, B_);
        attn_out_kernel<<<grid, 256>>>(tok, out);
    }
}

// round 4
// speedup vs baseline: 2.6295x; 1.5927x over previous
#include <cuda_runtime.h>
#include <cuda_bf16.h>
#include <cstdint>

// Problem shapes (fixed per reference)
#define B_  4
#define T_  64
#define L_  128
#define D_  768
#define H_  12
#define HD_ 64   // head dim

// -------------------- scratch (device globals; no allocation) --------------------
__device__ float g_kvproj[B_ * T_ * 2 * D_];            // [256,1536] rows=(b,t): [0,768)=k, [768,1536)=v
__device__ float g_M[(size_t)B_ * T_ * H_ * HD_ * HD_]; // [B,T,H,64,64]

// -------------------- kv projection: C[256,1536] = edu @ concat(Wk,Wv)^T --------------------
// BM=BN=64, BK=16, TM=TN=4, 256 threads. Each 64-col tile lies wholly in Wk or Wv.
__global__ void kvproj_kernel(const float* __restrict__ A, const float* __restrict__ Wk,
                              const float* __restrict__ Wv, float* __restrict__ C) {
    const int K = D_, N = 2 * D_;
    __shared__ float As[16][64 + 4];
    __shared__ float Bs[16][64 + 4];

    const int tid = threadIdx.x;
    const int tx  = tid % 16;
    const int ty  = tid / 16;
    const int row0 = blockIdx.y * 64;
    const int col0 = blockIdx.x * 64;

    // select weight half (uniform per block: 64 | 768)
    const float* Bbase = (col0 < D_) ? Wk : Wv;
    const int    bn0   = (col0 < D_) ? col0 : (col0 - D_);

    float acc[4][4];
#pragma unroll
    for (int i = 0; i < 4; i++)
#pragma unroll
        for (int j = 0; j < 4; j++) acc[i][j] = 0.0f;

    for (int k0 = 0; k0 < K; k0 += 16) {
        {
            int idx = tid;                    // 256 float4 slots = 64 rows x 4
            int r = idx / 4, kq = idx % 4;
            float4 v = *reinterpret_cast<const float4*>(&A[(size_t)(row0 + r) * K + k0 + kq * 4]);
            As[kq * 4 + 0][r] = v.x; As[kq * 4 + 1][r] = v.y;
            As[kq * 4 + 2][r] = v.z; As[kq * 4 + 3][r] = v.w;
        }
        {
            int idx = tid;
            int r = idx / 4, kq = idx % 4;
            float4 v = *reinterpret_cast<const float4*>(&Bbase[(size_t)(bn0 + r) * K + k0 + kq * 4]);
            Bs[kq * 4 + 0][r] = v.x; Bs[kq * 4 + 1][r] = v.y;
            Bs[kq * 4 + 2][r] = v.z; Bs[kq * 4 + 3][r] = v.w;
        }
        __syncthreads();

#pragma unroll
        for (int kk = 0; kk < 16; kk++) {
            float ar[4], br[4];
#pragma unroll
            for (int i = 0; i < 4; i++) ar[i] = As[kk][ty * 4 + i];
#pragma unroll
            for (int j = 0; j < 4; j++) br[j] = Bs[kk][tx * 4 + j];
#pragma unroll
            for (int i = 0; i < 4; i++)
#pragma unroll
                for (int j = 0; j < 4; j++) acc[i][j] += ar[i] * br[j];
        }
        __syncthreads();
    }

#pragma unroll
    for (int i = 0; i < 4; i++) {
        float4 v = make_float4(acc[i][0], acc[i][1], acc[i][2], acc[i][3]);
        *reinterpret_cast<float4*>(&C[(size_t)(row0 + ty * 4 + i) * N + col0 + tx * 4]) = v;
    }
}

// -------------------- speaker-segmented prefix sums: one block per (speaker, h, b) --------------------
// Walks u ascending; on speaker match, accumulates outer(k,v) and writes M[b,u,h].
__global__ void compute_M_kernel(const int* __restrict__ spk) {
    const int s = blockIdx.x, h = blockIdx.y, b = blockIdx.z;
    const int tid = threadIdx.x;   // 128

    __shared__ float kb[T_][HD_];
    __shared__ float vb[T_][HD_];
    __shared__ int sspk[T_];

    for (int i = tid; i < T_ * HD_; i += 128) {
        int u = i >> 6, d = i & 63;
        size_t rowb = (size_t)(b * T_ + u) * (2 * D_);
        kb[u][d] = g_kvproj[rowb + h * HD_ + d];
        vb[u][d] = g_kvproj[rowb + D_ + h * HD_ + d];
    }
    if (tid < T_) sspk[tid] = spk[b * T_ + tid];
    __syncthreads();

    const int d  = tid >> 1;
    const int e0 = (tid & 1) * 32;

    float acc[32];
#pragma unroll
    for (int e = 0; e < 32; e++) acc[e] = 0.0f;

    for (int u = 0; u < T_; u++) {
        if (sspk[u] != s) continue;
        float kd = kb[u][d];
#pragma unroll
        for (int e = 0; e < 32; e++) acc[e] += kd * vb[u][e0 + e];
        float* outp = g_M + ((size_t)((b * T_ + u) * H_ + h)) * (HD_ * HD_) + d * HD_ + e0;
#pragma unroll
        for (int e = 0; e < 32; e += 4)
            *reinterpret_cast<float4*>(&outp[e]) =
                make_float4(acc[e], acc[e + 1], acc[e + 2], acc[e + 3]);
    }
}

// -------------------- fused q-projection + apply (TF32 tensor cores) --------------------
// Block (x=h, y=bt): q_tile[128 tok x 64 dims] = tok_tile @ Wq_h^T  (K=768, double-buffered),
// then out_tile = tok_tile + q_tile @ M[b,t,h]  (K=64, same mma machinery).
//
// SMEM: 2 stages x (A 128x32 + B 64x32) tf32 words, pad-free XOR swizzle:
//   word(r,c) = r*32 + [((c&3)^(r&3))<<3] + [(c>>2) ^ ((r&1)<<2)]
// Conflict-free on float4-derived scalar stores and on LDS.128 fragment loads.

#define QBM 128
#define QBN 64
#define QBK 32
#define QSTG ((QBM + QBN) * QBK)   // 6144 words per stage

__device__ __forceinline__ uint32_t f32_to_tf32(float x) {
    uint32_t r;
    asm volatile("cvt.rna.tf32.f32 %0, %1;" : "=r"(r) : "f"(x));
    return r;
}

__device__ __forceinline__ void mma_tf32(float c[4], uint32_t a0, uint32_t a1,
                                         uint32_t a2, uint32_t a3,
                                         uint32_t b0, uint32_t b1) {
    asm volatile(
        "mma.sync.aligned.m16n8k8.row.col.f32.tf32.tf32.f32 "
        "{%0,%1,%2,%3}, {%4,%5,%6,%7}, {%8,%9}, {%0,%1,%2,%3};"
        : "+f"(c[0]), "+f"(c[1]), "+f"(c[2]), "+f"(c[3])
        : "r"(a0), "r"(a1), "r"(a2), "r"(a3), "r"(b0), "r"(b1));
}

__device__ __forceinline__ void sw_store(uint32_t* base, int r, int c, uint32_t v) {
    base[r * 32 + ((((c & 3) ^ (r & 3)) << 3) | ((c >> 2) ^ ((r & 1) << 2)))] = v;
}

// fragment load: row r, k-chunk c4 (lane&3), k-half h (ks pair). Returns 4 words:
// w = 2s+m  ->  k = 8*(2h+s) + 4m + c4
__device__ __forceinline__ uint4 frag_ld(const uint32_t* base, int r, int c4, int h) {
    int addr = r * 32 + ((c4 ^ (r & 3)) << 3) + (((h ^ r) & 1) << 2);
    return *reinterpret_cast<const uint4*>(base + addr);
}

// one BK=32 stage of warp-tile mma, accumulating into acc
__device__ __forceinline__ void stage_mma(const uint32_t* Asb, const uint32_t* Bsb,
                                          int warp_m, int warp_n, int gid, int c4,
                                          float acc[2][4][4]) {
#pragma unroll
    for (int h = 0; h < 2; h++) {
        uint4 af[2][2];
        uint4 bf[4];
#pragma unroll
        for (int mt = 0; mt < 2; mt++) {
            int r0 = warp_m * 32 + mt * 16 + gid;
            af[mt][0] = frag_ld(Asb, r0, c4, h);
            af[mt][1] = frag_ld(Asb, r0 + 8, c4, h);
        }
#pragma unroll
        for (int nt = 0; nt < 4; nt++) {
            int n = warp_n * 32 + nt * 8 + gid;
            bf[nt] = frag_ld(Bsb, n, c4, h);
        }
#pragma unroll
        for (int s = 0; s < 2; s++) {
#pragma unroll
            for (int mt = 0; mt < 2; mt++) {
#pragma unroll
                for (int nt = 0; nt < 4; nt++) {
                    const uint32_t* a0 = reinterpret_cast<const uint32_t*>(&af[mt][0]);
                    const uint32_t* a1 = reinterpret_cast<const uint32_t*>(&af[mt][1]);
                    const uint32_t* bb = reinterpret_cast<const uint32_t*>(&bf[nt]);
                    mma_tf32(acc[mt][nt],
                             a0[2 * s], a1[2 * s], a0[2 * s + 1], a1[2 * s + 1],
                             bb[2 * s], bb[2 * s + 1]);
                }
            }
        }
    }
}

__global__ __launch_bounds__(256, 2)
void qgemm_fused_kernel(const float* __restrict__ tok, const float* __restrict__ Wq,
                        const float* __restrict__ Mall, float* __restrict__ out) {
    __shared__ uint32_t smem[2 * QSTG];   // 48 KB

    const int tid  = threadIdx.x;
    const int warp = tid >> 5;
    const int lane = tid & 31;
    const int gid  = lane >> 2;
    const int c4   = lane & 3;
    const int warp_m = warp & 3;
    const int warp_n = warp >> 2;

    const int hblk = blockIdx.x;           // head 0..11
    const int bt   = blockIdx.y;           // 0..255
    const int row0 = bt * QBM;
    const int col0 = hblk * QBN;

    // per-thread global-load slots
    int ar[4], acq[4], br[2], bcq[2];
    const float* aptr[4];
    const float* bptr[2];
#pragma unroll
    for (int i = 0; i < 4; i++) {
        int idx = tid + i * 256;
        ar[i] = idx >> 3; acq[i] = idx & 7;
        aptr[i] = tok + (size_t)(row0 + ar[i]) * D_ + acq[i] * 4;
    }
#pragma unroll
    for (int i = 0; i < 2; i++) {
        int idx = tid + i * 256;
        br[i] = idx >> 3; bcq[i] = idx & 7;
        bptr[i] = Wq + (size_t)(col0 + br[i]) * D_ + bcq[i] * 4;
    }

    float cacc[2][4][4];
#pragma unroll
    for (int mt = 0; mt < 2; mt++)
#pragma unroll
        for (int nt = 0; nt < 4; nt++)
#pragma unroll
            for (int i = 0; i < 4; i++) cacc[mt][nt][i] = 0.0f;

    // prologue: load tile 0
    float4 av[4], bv[2];
#pragma unroll
    for (int i = 0; i < 4; i++) { av[i] = *reinterpret_cast<const float4*>(aptr[i]); aptr[i] += QBK; }
#pragma unroll
    for (int i = 0; i < 2; i++) { bv[i] = *reinterpret_cast<const float4*>(bptr[i]); bptr[i] += QBK; }

    const int NIT = D_ / QBK;   // 24
    int p = 0;
    for (int it = 0; it < NIT; it++) {
        uint32_t* Asb = smem + p * QSTG;
        uint32_t* Bsb = Asb + QBM * QBK;
        // store prefetched tile (convert to tf32, swizzled)
#pragma unroll
        for (int i = 0; i < 4; i++) {
            int c = acq[i] * 4;
            sw_store(Asb, ar[i], c + 0, f32_to_tf32(av[i].x));
            sw_store(Asb, ar[i], c + 1, f32_to_tf32(av[i].y));
            sw_store(Asb, ar[i], c + 2, f32_to_tf32(av[i].z));
            sw_store(Asb, ar[i], c + 3, f32_to_tf32(av[i].w));
        }
#pragma unroll
        for (int i = 0; i < 2; i++) {
            int c = bcq[i] * 4;
            sw_store(Bsb, br[i], c + 0, f32_to_tf32(bv[i].x));
            sw_store(Bsb, br[i], c + 1, f32_to_tf32(bv[i].y));
            sw_store(Bsb, br[i], c + 2, f32_to_tf32(bv[i].z));
            sw_store(Bsb, br[i], c + 3, f32_to_tf32(bv[i].w));
        }
        // prefetch next tile (overlaps with mma below)
        if (it + 1 < NIT) {
#pragma unroll
            for (int i = 0; i < 4; i++) { av[i] = *reinterpret_cast<const float4*>(aptr[i]); aptr[i] += QBK; }
#pragma unroll
            for (int i = 0; i < 2; i++) { bv[i] = *reinterpret_cast<const float4*>(bptr[i]); bptr[i] += QBK; }
        }
        __syncthreads();
        stage_mma(Asb, Bsb, warp_m, warp_n, gid, c4, cacc);
        p ^= 1;
    }

    // ---------------- phase 2: apply  out = tok + q @ M ----------------
    __syncthreads();   // everyone done reading smem before overwrite

    // write q (tf32) into A-areas: stage = d>>5 for k-col d
#pragma unroll
    for (int mt = 0; mt < 2; mt++) {
#pragma unroll
        for (int nt = 0; nt < 4; nt++) {
#pragma unroll
            for (int i = 0; i < 4; i++) {
                int r = warp_m * 32 + mt * 16 + gid + ((i >> 1) ? 8 : 0);
                int c = warp_n * 32 + nt * 8 + c4 * 2 + (i & 1);
                uint32_t* Asb = smem + (c >> 5) * QSTG;
                sw_store(Asb, r, c & 31, f32_to_tf32(cacc[mt][nt][i]));
            }
        }
    }
    // write M^T (tf32) into B-areas: B[n=e][k=d] = M[d][e]; stage = d>>5
    {
        const float* Mg = Mall + ((size_t)(bt * H_ + hblk)) * (HD_ * HD_);
#pragma unroll
        for (int i = 0; i < 16; i++) {
            int idx = tid + i * 256;         // 0..4095
            int d = idx >> 6, e = idx & 63;
            uint32_t v = f32_to_tf32(Mg[idx]);
            sw_store(smem + (d >> 5) * QSTG + QBM * QBK, e, d & 31, v);
        }
    }
    __syncthreads();

    // reuse cacc as output accumulator
#pragma unroll
    for (int mt = 0; mt < 2; mt++)
#pragma unroll
        for (int nt = 0; nt < 4; nt++)
#pragma unroll
            for (int i = 0; i < 4; i++) cacc[mt][nt][i] = 0.0f;

    stage_mma(smem,            smem + QBM * QBK,            warp_m, warp_n, gid, c4, cacc);
    stage_mma(smem + QSTG,     smem + QSTG + QBM * QBK,     warp_m, warp_n, gid, c4, cacc);

    // epilogue: out = tok + acc
#pragma unroll
    for (int mt = 0; mt < 2; mt++) {
#pragma unroll
        for (int nt = 0; nt < 4; nt++) {
            int row = row0 + warp_m * 32 + mt * 16 + gid;
            int col = col0 + warp_n * 32 + nt * 8 + c4 * 2;
            size_t a0 = (size_t)row * D_ + col;
            size_t a1 = (size_t)(row + 8) * D_ + col;
            float2 x0 = *reinterpret_cast<const float2*>(tok + a0);
            float2 x1 = *reinterpret_cast<const float2*>(tok + a1);
            *reinterpret_cast<float2*>(out + a0) =
                make_float2(cacc[mt][nt][0] + x0.x, cacc[mt][nt][1] + x0.y);
            *reinterpret_cast<float2*>(out + a1) =
                make_float2(cacc[mt][nt][2] + x1.x, cacc[mt][nt][3] + x1.y);
        }
    }
}

// -------------------- launch --------------------
extern "C" void kernel_launch(void* const* d_in, const int* in_sizes, int n_in,
                              void* d_out, int out_size) {
    const int*   spk = (const int*)d_in[1];
    const float* tok = (const float*)d_in[2];
    const float* edu = (const float*)d_in[3];
    const float* Wk  = (const float*)d_in[4];
    const float* Wv  = (const float*)d_in[5];
    const float* Wq  = (const float*)d_in[6];
    float* out = (float*)d_out;

    float* p_kvproj; cudaGetSymbolAddress((void**)&p_kvproj, g_kvproj);
    float* p_M;      cudaGetSymbolAddress((void**)&p_M,      g_M);

    // 1) kv projection (reads Wk/Wv directly)
    {
        dim3 grid((2 * D_) / 64, (B_ * T_) / 64);   // (24, 4)
        kvproj_kernel<<<grid, 256>>>(edu, Wk, Wv, p_kvproj);
    }

    // 2) speaker-segmented prefix sums of outer products
    {
        dim3 grid(8, H_, B_);                        // (speakers, heads, batch)
        compute_M_kernel<<<grid, 128>>>(spk);
    }

    // 3) fused q projection + apply + residual
    {
        dim3 grid(H_, B_ * T_);                      // (12, 256)
        qgemm_fused_kernel<<<grid, 256>>>(tok, Wq, p_M, out);
    }
}

// round 6
// speedup vs baseline: 2.7053x; 1.0288x over previous
#include <cuda_runtime.h>
#include <cuda_bf16.h>
#include <cstdint>

// Problem shapes (fixed per reference)
#define B_  4
#define T_  64
#define L_  128
#define D_  768
#define H_  12
#define HD_ 64   // head dim

// -------------------- scratch (device globals; no allocation) --------------------
__device__ float g_kvproj[B_ * T_ * 2 * D_];   // [256,1536] rows=(b,t): [0,768)=k, [768,1536)=v

// -------------------- kv projection: C[256,1536] = edu @ concat(Wk,Wv)^T --------------------
// BM=32, BN=64, BK=32, 256 threads, TM=2, TN=4. grid (24, 8) = 192 blocks.
__global__ void kvproj_kernel(const float* __restrict__ A, const float* __restrict__ Wk,
                              const float* __restrict__ Wv, float* __restrict__ C) {
    const int K = D_, N = 2 * D_;
    __shared__ float As[32][33];
    __shared__ float Bs[32][68];

    const int tid = threadIdx.x;
    const int tx  = tid & 15;
    const int ty  = tid >> 4;
    const int row0 = blockIdx.y * 32;
    const int col0 = blockIdx.x * 64;

    const float* Bbase = (col0 < D_) ? Wk : Wv;
    const int    bn0   = (col0 < D_) ? col0 : (col0 - D_);

    float acc[2][4];
#pragma unroll
    for (int i = 0; i < 2; i++)
#pragma unroll
        for (int j = 0; j < 4; j++) acc[i][j] = 0.0f;

    for (int k0 = 0; k0 < K; k0 += 32) {
        {   // A tile 32x32: 256 float4 slots, 1 per thread
            int r = tid >> 3, kq = tid & 7;
            float4 v = *reinterpret_cast<const float4*>(&A[(size_t)(row0 + r) * K + k0 + kq * 4]);
            As[kq * 4 + 0][r] = v.x; As[kq * 4 + 1][r] = v.y;
            As[kq * 4 + 2][r] = v.z; As[kq * 4 + 3][r] = v.w;
        }
#pragma unroll
        for (int i = 0; i < 2; i++) {   // B tile 64x32: 512 slots, 2 per thread
            int idx = tid + i * 256;
            int r = idx >> 3, kq = idx & 7;
            float4 v = *reinterpret_cast<const float4*>(&Bbase[(size_t)(bn0 + r) * K + k0 + kq * 4]);
            Bs[kq * 4 + 0][r] = v.x; Bs[kq * 4 + 1][r] = v.y;
            Bs[kq * 4 + 2][r] = v.z; Bs[kq * 4 + 3][r] = v.w;
        }
        __syncthreads();

#pragma unroll
        for (int kk = 0; kk < 32; kk++) {
            float ar[2];
            ar[0] = As[kk][ty * 2 + 0];
            ar[1] = As[kk][ty * 2 + 1];
            float4 b4 = *reinterpret_cast<const float4*>(&Bs[kk][tx * 4]);
            acc[0][0] += ar[0] * b4.x; acc[0][1] += ar[0] * b4.y;
            acc[0][2] += ar[0] * b4.z; acc[0][3] += ar[0] * b4.w;
            acc[1][0] += ar[1] * b4.x; acc[1][1] += ar[1] * b4.y;
            acc[1][2] += ar[1] * b4.z; acc[1][3] += ar[1] * b4.w;
        }
        __syncthreads();
    }

#pragma unroll
    for (int i = 0; i < 2; i++) {
        float4 v = make_float4(acc[i][0], acc[i][1], acc[i][2], acc[i][3]);
        *reinterpret_cast<float4*>(&C[(size_t)(row0 + ty * 2 + i) * N + col0 + tx * 4]) = v;
    }
}

// -------------------- fused q-projection + M build + apply (TF32 tensor cores) --------------------
// Block (x=h, y=bt): q_tile[128 tok x 64] = tok_tile @ Wq_h^T (K=768, double-buffered tf32 mma);
// then builds M[b,t,h] = prefix of outer(k,v) over same-speaker turns IN-BLOCK (fp32),
// then out = tok + q_tile @ M (tf32 mma), residual epilogue.
//
// Dynamic SMEM (words): [0, 2*QSTG) mma stages; then kb[64*64], vb[64*64] fp32; then spk[64].

#define QBM 128
#define QBN 64
#define QBK 32
#define QSTG ((QBM + QBN) * QBK)           // 6144 words per stage
#define KBW  (2 * QSTG)                    // kb offset (words)
#define VBW  (KBW + T_ * HD_)              // vb offset
#define SPKW (VBW + T_ * HD_)              // spk offset
#define SMEM_WORDS (SPKW + T_)
#define SMEM_BYTES (SMEM_WORDS * 4)        // 82432 B

__device__ __forceinline__ uint32_t f32_to_tf32(float x) {
    uint32_t r;
    asm volatile("cvt.rna.tf32.f32 %0, %1;" : "=r"(r) : "f"(x));
    return r;
}

__device__ __forceinline__ void mma_tf32(float c[4], uint32_t a0, uint32_t a1,
                                         uint32_t a2, uint32_t a3,
                                         uint32_t b0, uint32_t b1) {
    asm volatile(
        "mma.sync.aligned.m16n8k8.row.col.f32.tf32.tf32.f32 "
        "{%0,%1,%2,%3}, {%4,%5,%6,%7}, {%8,%9}, {%0,%1,%2,%3};"
        : "+f"(c[0]), "+f"(c[1]), "+f"(c[2]), "+f"(c[3])
        : "r"(a0), "r"(a1), "r"(a2), "r"(a3), "r"(b0), "r"(b1));
}

__device__ __forceinline__ void sw_store(uint32_t* base, int r, int c, uint32_t v) {
    base[r * 32 + ((((c & 3) ^ (r & 3)) << 3) | ((c >> 2) ^ ((r & 1) << 2)))] = v;
}

__device__ __forceinline__ uint4 frag_ld(const uint32_t* base, int r, int c4, int h) {
    int addr = r * 32 + ((c4 ^ (r & 3)) << 3) + (((h ^ r) & 1) << 2);
    return *reinterpret_cast<const uint4*>(base + addr);
}

__device__ __forceinline__ void stage_mma(const uint32_t* Asb, const uint32_t* Bsb,
                                          int warp_m, int warp_n, int gid, int c4,
                                          float acc[2][4][4]) {
#pragma unroll
    for (int h = 0; h < 2; h++) {
        uint4 af[2][2];
        uint4 bf[4];
#pragma unroll
        for (int mt = 0; mt < 2; mt++) {
            int r0 = warp_m * 32 + mt * 16 + gid;
            af[mt][0] = frag_ld(Asb, r0, c4, h);
            af[mt][1] = frag_ld(Asb, r0 + 8, c4, h);
        }
#pragma unroll
        for (int nt = 0; nt < 4; nt++) {
            int n = warp_n * 32 + nt * 8 + gid;
            bf[nt] = frag_ld(Bsb, n, c4, h);
        }
#pragma unroll
        for (int s = 0; s < 2; s++) {
#pragma unroll
            for (int mt = 0; mt < 2; mt++) {
#pragma unroll
                for (int nt = 0; nt < 4; nt++) {
                    const uint32_t* a0 = reinterpret_cast<const uint32_t*>(&af[mt][0]);
                    const uint32_t* a1 = reinterpret_cast<const uint32_t*>(&af[mt][1]);
                    const uint32_t* bb = reinterpret_cast<const uint32_t*>(&bf[nt]);
                    mma_tf32(acc[mt][nt],
                             a0[2 * s], a1[2 * s], a0[2 * s + 1], a1[2 * s + 1],
                             bb[2 * s], bb[2 * s + 1]);
                }
            }
        }
    }
}

__global__ __launch_bounds__(256, 2)
void qgemm_fused_kernel(const float* __restrict__ tok, const float* __restrict__ Wq,
                        const int* __restrict__ spk, float* __restrict__ out) {
    extern __shared__ uint32_t smem[];

    const int tid  = threadIdx.x;
    const int warp = tid >> 5;
    const int lane = tid & 31;
    const int gid  = lane >> 2;
    const int c4   = lane & 3;
    const int warp_m = warp & 3;
    const int warp_n = warp >> 2;

    const int hblk = blockIdx.x;           // head 0..11
    const int bt   = blockIdx.y;           // 0..255
    const int b    = bt >> 6;
    const int tloc = bt & 63;
    const int row0 = bt * QBM;
    const int col0 = hblk * QBN;

    // per-thread global-load slots
    int ar[4], acq[4], br[2], bcq[2];
    const float* aptr[4];
    const float* bptr[2];
#pragma unroll
    for (int i = 0; i < 4; i++) {
        int idx = tid + i * 256;
        ar[i] = idx >> 3; acq[i] = idx & 7;
        aptr[i] = tok + (size_t)(row0 + ar[i]) * D_ + acq[i] * 4;
    }
#pragma unroll
    for (int i = 0; i < 2; i++) {
        int idx = tid + i * 256;
        br[i] = idx >> 3; bcq[i] = idx & 7;
        bptr[i] = Wq + (size_t)(col0 + br[i]) * D_ + bcq[i] * 4;
    }

    float cacc[2][4][4];
#pragma unroll
    for (int mt = 0; mt < 2; mt++)
#pragma unroll
        for (int nt = 0; nt < 4; nt++)
#pragma unroll
            for (int i = 0; i < 4; i++) cacc[mt][nt][i] = 0.0f;

    // prologue: load tile 0
    float4 av[4], bv[2];
#pragma unroll
    for (int i = 0; i < 4; i++) { av[i] = *reinterpret_cast<const float4*>(aptr[i]); aptr[i] += QBK; }
#pragma unroll
    for (int i = 0; i < 2; i++) { bv[i] = *reinterpret_cast<const float4*>(bptr[i]); bptr[i] += QBK; }

    const int NIT = D_ / QBK;   // 24
    int p = 0;
    for (int it = 0; it < NIT; it++) {
        uint32_t* Asb = smem + p * QSTG;
        uint32_t* Bsb = Asb + QBM * QBK;
#pragma unroll
        for (int i = 0; i < 4; i++) {
            int c = acq[i] * 4;
            sw_store(Asb, ar[i], c + 0, f32_to_tf32(av[i].x));
            sw_store(Asb, ar[i], c + 1, f32_to_tf32(av[i].y));
            sw_store(Asb, ar[i], c + 2, f32_to_tf32(av[i].z));
            sw_store(Asb, ar[i], c + 3, f32_to_tf32(av[i].w));
        }
#pragma unroll
        for (int i = 0; i < 2; i++) {
            int c = bcq[i] * 4;
            sw_store(Bsb, br[i], c + 0, f32_to_tf32(bv[i].x));
            sw_store(Bsb, br[i], c + 1, f32_to_tf32(bv[i].y));
            sw_store(Bsb, br[i], c + 2, f32_to_tf32(bv[i].z));
            sw_store(Bsb, br[i], c + 3, f32_to_tf32(bv[i].w));
        }
        if (it + 1 < NIT) {
#pragma unroll
            for (int i = 0; i < 4; i++) { av[i] = *reinterpret_cast<const float4*>(aptr[i]); aptr[i] += QBK; }
#pragma unroll
            for (int i = 0; i < 2; i++) { bv[i] = *reinterpret_cast<const float4*>(bptr[i]); bptr[i] += QBK; }
        }
        __syncthreads();
        stage_mma(Asb, Bsb, warp_m, warp_n, gid, c4, cacc);
        p ^= 1;
    }

    // ---------------- phase 2: build M in-block, then out = tok + q @ M ----------------
    float* kbs = reinterpret_cast<float*>(smem + KBW);
    float* vbs = reinterpret_cast<float*>(smem + VBW);
    int*   sspk = reinterpret_cast<int*>(smem + SPKW);

    // stage k,v for this (b, h) into scratch smem (region untouched by main loop)
    {
        const float* kvb = g_kvproj + (size_t)(b * T_) * (2 * D_);
#pragma unroll
        for (int i = 0; i < 4; i++) {
            int idx = tid + i * 256;          // 0..1023 float4 slots
            int u = idx >> 4, dq = idx & 15;
            *reinterpret_cast<float4*>(&kbs[u * HD_ + dq * 4]) =
                *reinterpret_cast<const float4*>(&kvb[(size_t)u * (2 * D_) + hblk * HD_ + dq * 4]);
            *reinterpret_cast<float4*>(&vbs[u * HD_ + dq * 4]) =
                *reinterpret_cast<const float4*>(&kvb[(size_t)u * (2 * D_) + D_ + hblk * HD_ + dq * 4]);
        }
        if (tid < T_) sspk[tid] = spk[b * T_ + tid];
    }
    __syncthreads();   // main-loop smem reads done; kb/vb/spk visible

    // write q (tf32) into A-areas of both stages (k-col d selects stage d>>5)
#pragma unroll
    for (int mt = 0; mt < 2; mt++) {
#pragma unroll
        for (int nt = 0; nt < 4; nt++) {
#pragma unroll
            for (int i = 0; i < 4; i++) {
                int r = warp_m * 32 + mt * 16 + gid + ((i >> 1) ? 8 : 0);
                int c = warp_n * 32 + nt * 8 + c4 * 2 + (i & 1);
                uint32_t* Asb = smem + (c >> 5) * QSTG;
                sw_store(Asb, r, c & 31, f32_to_tf32(cacc[mt][nt][i]));
            }
        }
    }

    // build M[d][e] = sum_{u<=t, spk match} k[u][d]*v[u][e]  (fp32, ascending u)
    {
        const int d  = tid >> 2;
        const int e0 = (tid & 3) * 16;
        const int myspk = sspk[tloc];
        float macc[16];
#pragma unroll
        for (int j = 0; j < 16; j++) macc[j] = 0.0f;

        for (int u = 0; u <= tloc; u++) {
            if (sspk[u] != myspk) continue;
            float kd = kbs[u * HD_ + d];
#pragma unroll
            for (int j4 = 0; j4 < 4; j4++) {
                float4 v4 = *reinterpret_cast<const float4*>(&vbs[u * HD_ + e0 + j4 * 4]);
                macc[j4 * 4 + 0] += kd * v4.x;
                macc[j4 * 4 + 1] += kd * v4.y;
                macc[j4 * 4 + 2] += kd * v4.z;
                macc[j4 * 4 + 3] += kd * v4.w;
            }
        }
        // store M^T into B-areas: Bs[n=e][k=d] = M[d][e], stage = d>>5
        uint32_t* Bbase = smem + (d >> 5) * QSTG + QBM * QBK;
#pragma unroll
        for (int j = 0; j < 16; j++) {
            sw_store(Bbase, e0 + j, d & 31, f32_to_tf32(macc[j]));
        }
    }
    __syncthreads();

    // apply: acc = q @ M over K=64 (two BK=32 stages)
#pragma unroll
    for (int mt = 0; mt < 2; mt++)
#pragma unroll
        for (int nt = 0; nt < 4; nt++)
#pragma unroll
            for (int i = 0; i < 4; i++) cacc[mt][nt][i] = 0.0f;

    stage_mma(smem,        smem + QBM * QBK,        warp_m, warp_n, gid, c4, cacc);
    stage_mma(smem + QSTG, smem + QSTG + QBM * QBK, warp_m, warp_n, gid, c4, cacc);

    // epilogue: out = tok + acc
#pragma unroll
    for (int mt = 0; mt < 2; mt++) {
#pragma unroll
        for (int nt = 0; nt < 4; nt++) {
            int row = row0 + warp_m * 32 + mt * 16 + gid;
            int col = col0 + warp_n * 32 + nt * 8 + c4 * 2;
            size_t a0 = (size_t)row * D_ + col;
            size_t a1 = (size_t)(row + 8) * D_ + col;
            float2 x0 = *reinterpret_cast<const float2*>(tok + a0);
            float2 x1 = *reinterpret_cast<const float2*>(tok + a1);
            *reinterpret_cast<float2*>(out + a0) =
                make_float2(cacc[mt][nt][0] + x0.x, cacc[mt][nt][1] + x0.y);
            *reinterpret_cast<float2*>(out + a1) =
                make_float2(cacc[mt][nt][2] + x1.x, cacc[mt][nt][3] + x1.y);
        }
    }
}

// -------------------- launch --------------------
extern "C" void kernel_launch(void* const* d_in, const int* in_sizes, int n_in,
                              void* d_out, int out_size) {
    const int*   spk = (const int*)d_in[1];
    const float* tok = (const float*)d_in[2];
    const float* edu = (const float*)d_in[3];
    const float* Wk  = (const float*)d_in[4];
    const float* Wv  = (const float*)d_in[5];
    const float* Wq  = (const float*)d_in[6];
    float* out = (float*)d_out;

    float* p_kvproj; cudaGetSymbolAddress((void**)&p_kvproj, g_kvproj);

    // unconditional (idempotent, capture-safe; no static guards per harness rules)
    cudaFuncSetAttribute(qgemm_fused_kernel,
                         cudaFuncAttributeMaxDynamicSharedMemorySize, SMEM_BYTES);

    // 1) kv projection
    {
        dim3 grid((2 * D_) / 64, (B_ * T_) / 32);   // (24, 8)
        kvproj_kernel<<<grid, 256>>>(edu, Wk, Wv, p_kvproj);
    }

    // 2) fused q projection + M build + apply + residual
    {
        dim3 grid(H_, B_ * T_);                      // (12, 256)
        qgemm_fused_kernel<<<grid, 256, SMEM_BYTES>>>(tok, Wq, spk, out);
    }
}

// round 8
// speedup vs baseline: 3.9216x; 1.4496x over previous
#include <cuda_runtime.h>
#include <cuda_fp16.h>
#include <cstdint>

// Problem shapes (fixed per reference)
#define B_  4
#define T_  64
#define L_  128
#define D_  768
#define H_  12
#define HD_ 64   // head dim

// -------------------- scratch (device globals; no allocation) --------------------
__device__ float g_kvproj[B_ * T_ * 2 * D_];   // [256,1536] rows=(b,t): [0,768)=k, [768,1536)=v

// -------------------- kv projection: C[256,1536] = edu @ concat(Wk,Wv)^T --------------------
__global__ void kvproj_kernel(const float* __restrict__ A, const float* __restrict__ Wk,
                              const float* __restrict__ Wv, float* __restrict__ C) {
    const int K = D_, N = 2 * D_;
    __shared__ float As[32][33];
    __shared__ float Bs[32][68];

    const int tid = threadIdx.x;
    const int tx  = tid & 15;
    const int ty  = tid >> 4;
    const int row0 = blockIdx.y * 32;
    const int col0 = blockIdx.x * 64;

    const float* Bbase = (col0 < D_) ? Wk : Wv;
    const int    bn0   = (col0 < D_) ? col0 : (col0 - D_);

    float acc[2][4];
#pragma unroll
    for (int i = 0; i < 2; i++)
#pragma unroll
        for (int j = 0; j < 4; j++) acc[i][j] = 0.0f;

    for (int k0 = 0; k0 < K; k0 += 32) {
        {
            int r = tid >> 3, kq = tid & 7;
            float4 v = *reinterpret_cast<const float4*>(&A[(size_t)(row0 + r) * K + k0 + kq * 4]);
            As[kq * 4 + 0][r] = v.x; As[kq * 4 + 1][r] = v.y;
            As[kq * 4 + 2][r] = v.z; As[kq * 4 + 3][r] = v.w;
        }
#pragma unroll
        for (int i = 0; i < 2; i++) {
            int idx = tid + i * 256;
            int r = idx >> 3, kq = idx & 7;
            float4 v = *reinterpret_cast<const float4*>(&Bbase[(size_t)(bn0 + r) * K + k0 + kq * 4]);
            Bs[kq * 4 + 0][r] = v.x; Bs[kq * 4 + 1][r] = v.y;
            Bs[kq * 4 + 2][r] = v.z; Bs[kq * 4 + 3][r] = v.w;
        }
        __syncthreads();

#pragma unroll
        for (int kk = 0; kk < 32; kk++) {
            float ar[2];
            ar[0] = As[kk][ty * 2 + 0];
            ar[1] = As[kk][ty * 2 + 1];
            float4 b4 = *reinterpret_cast<const float4*>(&Bs[kk][tx * 4]);
            acc[0][0] += ar[0] * b4.x; acc[0][1] += ar[0] * b4.y;
            acc[0][2] += ar[0] * b4.z; acc[0][3] += ar[0] * b4.w;
            acc[1][0] += ar[1] * b4.x; acc[1][1] += ar[1] * b4.y;
            acc[1][2] += ar[1] * b4.z; acc[1][3] += ar[1] * b4.w;
        }
        __syncthreads();
    }

#pragma unroll
    for (int i = 0; i < 2; i++) {
        float4 v = make_float4(acc[i][0], acc[i][1], acc[i][2], acc[i][3]);
        *reinterpret_cast<float4*>(&C[(size_t)(row0 + ty * 2 + i) * N + col0 + tx * 4]) = v;
    }
}

// -------------------- fused q-projection + M build + apply (FP16 m16n8k16 tensor cores) --------------------
// Block (x=h, y=bt): q[128x64] = tok @ Wq_h^T (K=768, fp32 acc), then M[b,t,h] built in-block (fp32),
// then out = tok + q @ M, residual epilogue. fp16 smem, 16 half2-words per 32-k row, swizzle:
//   pos(r,w) = r*16 + ((w&3)^(r&3))*4 + (w>>2)    (uint4 fragment load = all 4 k-steps)

#define QBM 128
#define QBN 64
#define QBK 32
#define A16W   (QBM * 16)                  // 2048 words per A stage
#define QSTG16 ((QBM + QBN) * 16)          // 3072 words per stage
#define KBW    (2 * QSTG16)                // kb offset (words)
#define VBW    (KBW + T_ * HD_)
#define SPKW   (VBW + T_ * HD_)
#define SMEM_WORDS (SPKW + T_)
#define SMEM_BYTES (SMEM_WORDS * 4)        // 57600 B

__device__ __forceinline__ uint32_t pack_h2(float lo, float hi) {
    __half2 h = __floats2half2_rn(lo, hi);   // .x = lo (low 16 bits)
    return *reinterpret_cast<uint32_t*>(&h);
}

__device__ __forceinline__ void mma_f16(float c[4], uint32_t a0, uint32_t a1,
                                        uint32_t a2, uint32_t a3,
                                        uint32_t b0, uint32_t b1) {
    asm volatile(
        "mma.sync.aligned.m16n8k16.row.col.f32.f16.f16.f32 "
        "{%0,%1,%2,%3}, {%4,%5,%6,%7}, {%8,%9}, {%0,%1,%2,%3};"
        : "+f"(c[0]), "+f"(c[1]), "+f"(c[2]), "+f"(c[3])
        : "r"(a0), "r"(a1), "r"(a2), "r"(a3), "r"(b0), "r"(b1));
}

// store half2 word w (0..15) of row r
__device__ __forceinline__ void sw_store16(uint32_t* base, int r, int w, uint32_t v) {
    base[r * 16 + ((((w & 3) ^ (r & 3)) << 2) | (w >> 2))] = v;
}

// fragment load: row r, k-chunk c4. Component j holds k = 2*c4 + 8*j (pair).
__device__ __forceinline__ uint4 frag_ld16(const uint32_t* base, int r, int c4) {
    return *reinterpret_cast<const uint4*>(base + r * 16 + ((c4 ^ (r & 3)) << 2));
}

// one BK=32 stage: 16 mma m16n8k16 per thread
__device__ __forceinline__ void stage_mma16(const uint32_t* Asb, const uint32_t* Bsb,
                                            int warp_m, int warp_n, int gid, int c4,
                                            float acc[2][4][4]) {
    uint4 af[2][2];
    uint4 bf[4];
#pragma unroll
    for (int mt = 0; mt < 2; mt++) {
        int r0 = warp_m * 32 + mt * 16 + gid;
        af[mt][0] = frag_ld16(Asb, r0, c4);
        af[mt][1] = frag_ld16(Asb, r0 + 8, c4);
    }
#pragma unroll
    for (int nt = 0; nt < 4; nt++) {
        int n = warp_n * 32 + nt * 8 + gid;
        bf[nt] = frag_ld16(Bsb, n, c4);
    }
#pragma unroll
    for (int ks = 0; ks < 2; ks++) {
#pragma unroll
        for (int mt = 0; mt < 2; mt++) {
#pragma unroll
            for (int nt = 0; nt < 4; nt++) {
                const uint32_t* a0 = reinterpret_cast<const uint32_t*>(&af[mt][0]);
                const uint32_t* a1 = reinterpret_cast<const uint32_t*>(&af[mt][1]);
                const uint32_t* bb = reinterpret_cast<const uint32_t*>(&bf[nt]);
                mma_f16(acc[mt][nt],
                        a0[2 * ks], a1[2 * ks], a0[2 * ks + 1], a1[2 * ks + 1],
                        bb[2 * ks], bb[2 * ks + 1]);
            }
        }
    }
}

__global__ __launch_bounds__(256, 2)
void qgemm_fused_kernel(const float* __restrict__ tok, const float* __restrict__ Wq,
                        const int* __restrict__ spk, float* __restrict__ out) {
    extern __shared__ uint32_t smem[];

    const int tid  = threadIdx.x;
    const int warp = tid >> 5;
    const int lane = tid & 31;
    const int gid  = lane >> 2;
    const int c4   = lane & 3;
    const int warp_m = warp & 3;
    const int warp_n = warp >> 2;

    const int hblk = blockIdx.x;
    const int bt   = blockIdx.y;
    const int b    = bt >> 6;
    const int tloc = bt & 63;
    const int row0 = bt * QBM;
    const int col0 = hblk * QBN;

    int ar[4], acq[4], br[2], bcq[2];
    const float* aptr[4];
    const float* bptr[2];
#pragma unroll
    for (int i = 0; i < 4; i++) {
        int idx = tid + i * 256;
        ar[i] = idx >> 3; acq[i] = idx & 7;
        aptr[i] = tok + (size_t)(row0 + ar[i]) * D_ + acq[i] * 4;
    }
#pragma unroll
    for (int i = 0; i < 2; i++) {
        int idx = tid + i * 256;
        br[i] = idx >> 3; bcq[i] = idx & 7;
        bptr[i] = Wq + (size_t)(col0 + br[i]) * D_ + bcq[i] * 4;
    }

    float cacc[2][4][4];
#pragma unroll
    for (int mt = 0; mt < 2; mt++)
#pragma unroll
        for (int nt = 0; nt < 4; nt++)
#pragma unroll
            for (int i = 0; i < 4; i++) cacc[mt][nt][i] = 0.0f;

    float4 av[4], bv[2];
#pragma unroll
    for (int i = 0; i < 4; i++) { av[i] = *reinterpret_cast<const float4*>(aptr[i]); aptr[i] += QBK; }
#pragma unroll
    for (int i = 0; i < 2; i++) { bv[i] = *reinterpret_cast<const float4*>(bptr[i]); bptr[i] += QBK; }

    const int NIT = D_ / QBK;   // 24
    int p = 0;
    for (int it = 0; it < NIT; it++) {
        uint32_t* Asb = smem + p * QSTG16;
        uint32_t* Bsb = Asb + A16W;
#pragma unroll
        for (int i = 0; i < 4; i++) {
            int w = acq[i] * 2;       // float cols acq*4.. -> half2 words acq*2, acq*2+1
            sw_store16(Asb, ar[i], w,     pack_h2(av[i].x, av[i].y));
            sw_store16(Asb, ar[i], w + 1, pack_h2(av[i].z, av[i].w));
        }
#pragma unroll
        for (int i = 0; i < 2; i++) {
            int w = bcq[i] * 2;
            sw_store16(Bsb, br[i], w,     pack_h2(bv[i].x, bv[i].y));
            sw_store16(Bsb, br[i], w + 1, pack_h2(bv[i].z, bv[i].w));
        }
        if (it + 1 < NIT) {
#pragma unroll
            for (int i = 0; i < 4; i++) { av[i] = *reinterpret_cast<const float4*>(aptr[i]); aptr[i] += QBK; }
#pragma unroll
            for (int i = 0; i < 2; i++) { bv[i] = *reinterpret_cast<const float4*>(bptr[i]); bptr[i] += QBK; }
        }
        __syncthreads();
        stage_mma16(Asb, Bsb, warp_m, warp_n, gid, c4, cacc);
        p ^= 1;
    }

    // ---------------- phase 2: build M in-block, then out = tok + q @ M ----------------
    float* kbs  = reinterpret_cast<float*>(smem + KBW);
    float* vbs  = reinterpret_cast<float*>(smem + VBW);
    int*   sspk = reinterpret_cast<int*>(smem + SPKW);

    // stage k,v for this (b,h): region disjoint from mma stages, safe pre-sync
    {
        const float* kvb = g_kvproj + (size_t)(b * T_) * (2 * D_);
#pragma unroll
        for (int i = 0; i < 4; i++) {
            int idx = tid + i * 256;
            int u = idx >> 4, dq = idx & 15;
            *reinterpret_cast<float4*>(&kbs[u * HD_ + dq * 4]) =
                *reinterpret_cast<const float4*>(&kvb[(size_t)u * (2 * D_) + hblk * HD_ + dq * 4]);
            *reinterpret_cast<float4*>(&vbs[u * HD_ + dq * 4]) =
                *reinterpret_cast<const float4*>(&kvb[(size_t)u * (2 * D_) + D_ + hblk * HD_ + dq * 4]);
        }
        if (tid < T_) sspk[tid] = spk[b * T_ + tid];
    }
    __syncthreads();   // main-loop smem reads done; kb/vb/spk visible

    // write q (fp16) into A-areas: col pair (c_even, c_even+1) -> one half2 word.
    // c_even = warp_n*32 + nt*8 + c4*2; stage = warp_n; local word = nt*4 + c4.
    {
        uint32_t* Asb = smem + warp_n * QSTG16;
#pragma unroll
        for (int mt = 0; mt < 2; mt++) {
#pragma unroll
            for (int nt = 0; nt < 4; nt++) {
                int r = warp_m * 32 + mt * 16 + gid;
                int w = nt * 4 + c4;
                sw_store16(Asb, r,     w, pack_h2(cacc[mt][nt][0], cacc[mt][nt][1]));
                sw_store16(Asb, r + 8, w, pack_h2(cacc[mt][nt][2], cacc[mt][nt][3]));
            }
        }
    }

    // build M[d][e] (fp32, ascending u); thread: d-pair dp = tid>>3, e-chunk = (tid&7)*8
    {
        const int dp = tid >> 3;           // 0..31 -> d0 = 2dp, d1 = 2dp+1
        const int e0 = (tid & 7) * 8;
        const int d0 = dp * 2;
        const int myspk = sspk[tloc];
        float m0[8], m1[8];
#pragma unroll
        for (int j = 0; j < 8; j++) { m0[j] = 0.0f; m1[j] = 0.0f; }

        for (int u = 0; u <= tloc; u++) {
            if (sspk[u] != myspk) continue;
            float kd0 = kbs[u * HD_ + d0];
            float kd1 = kbs[u * HD_ + d0 + 1];
#pragma unroll
            for (int j4 = 0; j4 < 2; j4++) {
                float4 v4 = *reinterpret_cast<const float4*>(&vbs[u * HD_ + e0 + j4 * 4]);
                m0[j4 * 4 + 0] += kd0 * v4.x; m1[j4 * 4 + 0] += kd1 * v4.x;
                m0[j4 * 4 + 1] += kd0 * v4.y; m1[j4 * 4 + 1] += kd1 * v4.y;
                m0[j4 * 4 + 2] += kd0 * v4.z; m1[j4 * 4 + 2] += kd1 * v4.z;
                m0[j4 * 4 + 3] += kd0 * v4.w; m1[j4 * 4 + 3] += kd1 * v4.w;
            }
        }
        // store M^T as fp16 into B-areas: B[row=e][k-word dp&15], stage dp>>4.
        uint32_t* Bbase = smem + (dp >> 4) * QSTG16 + A16W;
#pragma unroll
        for (int j = 0; j < 8; j++) {
            sw_store16(Bbase, e0 + j, dp & 15, pack_h2(m0[j], m1[j]));
        }
    }
    __syncthreads();

    // apply: acc = q @ M over K=64 (two BK=32 stages)
#pragma unroll
    for (int mt = 0; mt < 2; mt++)
#pragma unroll
        for (int nt = 0; nt < 4; nt++)
#pragma unroll
            for (int i = 0; i < 4; i++) cacc[mt][nt][i] = 0.0f;

    stage_mma16(smem,          smem + A16W,          warp_m, warp_n, gid, c4, cacc);
    stage_mma16(smem + QSTG16, smem + QSTG16 + A16W, warp_m, warp_n, gid, c4, cacc);

    // epilogue: out = tok + acc
#pragma unroll
    for (int mt = 0; mt < 2; mt++) {
#pragma unroll
        for (int nt = 0; nt < 4; nt++) {
            int row = row0 + warp_m * 32 + mt * 16 + gid;
            int col = col0 + warp_n * 32 + nt * 8 + c4 * 2;
            size_t a0 = (size_t)row * D_ + col;
            size_t a1 = (size_t)(row + 8) * D_ + col;
            float2 x0 = *reinterpret_cast<const float2*>(tok + a0);
            float2 x1 = *reinterpret_cast<const float2*>(tok + a1);
            *reinterpret_cast<float2*>(out + a0) =
                make_float2(cacc[mt][nt][0] + x0.x, cacc[mt][nt][1] + x0.y);
            *reinterpret_cast<float2*>(out + a1) =
                make_float2(cacc[mt][nt][2] + x1.x, cacc[mt][nt][3] + x1.y);
        }
    }
}

// -------------------- launch --------------------
extern "C" void kernel_launch(void* const* d_in, const int* in_sizes, int n_in,
                              void* d_out, int out_size) {
    const int*   spk = (const int*)d_in[1];
    const float* tok = (const float*)d_in[2];
    const float* edu = (const float*)d_in[3];
    const float* Wk  = (const float*)d_in[4];
    const float* Wv  = (const float*)d_in[5];
    const float* Wq  = (const float*)d_in[6];
    float* out = (float*)d_out;

    float* p_kvproj; cudaGetSymbolAddress((void**)&p_kvproj, g_kvproj);

    cudaFuncSetAttribute(qgemm_fused_kernel,
                         cudaFuncAttributeMaxDynamicSharedMemorySize, SMEM_BYTES);

    // 1) kv projection
    {
        dim3 grid((2 * D_) / 64, (B_ * T_) / 32);   // (24, 8)
        kvproj_kernel<<<grid, 256>>>(edu, Wk, Wv, p_kvproj);
    }

    // 2) fused q projection + M build + apply + residual
    {
        dim3 grid(H_, B_ * T_);                      // (12, 256)
        qgemm_fused_kernel<<<grid, 256, SMEM_BYTES>>>(tok, Wq, spk, out);
    }
}

// round 10
// speedup vs baseline: 4.3204x; 1.1017x over previous
#include <cuda_runtime.h>
#include <cuda_fp16.h>
#include <cstdint>

// Problem shapes (fixed per reference)
#define B_  4
#define T_  64
#define L_  128
#define D_  768
#define H_  12
#define HD_ 64   // head dim

// -------------------- scratch (device globals; no allocation) --------------------
__device__ float  g_kvproj[B_ * T_ * 2 * D_];            // fp32 k|v rows=(b,t)
__device__ __half g_tokh[(size_t)B_ * T_ * L_ * D_];     // fp16 token embeddings
__device__ __half g_Wqh[D_ * D_];                        // fp16 Wq

__device__ __forceinline__ uint32_t pack_h2(float lo, float hi) {
    __half2 h = __floats2half2_rn(lo, hi);
    return *reinterpret_cast<uint32_t*>(&h);
}

// -------------------- fp32 -> fp16 pre-convert (tok, Wq) --------------------
__global__ void tofp16_kernel(const float* __restrict__ tok, const float* __restrict__ Wq) {
    const size_t NT = (size_t)B_ * T_ * L_ * D_;
    size_t i = ((size_t)blockIdx.x * 256 + threadIdx.x) * 8;
    if (i < NT) {
        float4 a = *reinterpret_cast<const float4*>(tok + i);
        float4 b = *reinterpret_cast<const float4*>(tok + i + 4);
        uint4 o;
        o.x = pack_h2(a.x, a.y); o.y = pack_h2(a.z, a.w);
        o.z = pack_h2(b.x, b.y); o.w = pack_h2(b.z, b.w);
        *reinterpret_cast<uint4*>(g_tokh + i) = o;
    } else {
        size_t j = i - NT;
        if (j < (size_t)D_ * D_) {
            float4 a = *reinterpret_cast<const float4*>(Wq + j);
            float4 b = *reinterpret_cast<const float4*>(Wq + j + 4);
            uint4 o;
            o.x = pack_h2(a.x, a.y); o.y = pack_h2(a.z, a.w);
            o.z = pack_h2(b.x, b.y); o.w = pack_h2(b.z, b.w);
            *reinterpret_cast<uint4*>(g_Wqh + j) = o;
        }
    }
}

// -------------------- kv projection (fp32, unchanged) --------------------
__global__ void kvproj_kernel(const float* __restrict__ A, const float* __restrict__ Wk,
                              const float* __restrict__ Wv, float* __restrict__ C) {
    const int K = D_, N = 2 * D_;
    __shared__ float As[32][33];
    __shared__ float Bs[32][68];

    const int tid = threadIdx.x;
    const int tx  = tid & 15;
    const int ty  = tid >> 4;
    const int row0 = blockIdx.y * 32;
    const int col0 = blockIdx.x * 64;

    const float* Bbase = (col0 < D_) ? Wk : Wv;
    const int    bn0   = (col0 < D_) ? col0 : (col0 - D_);

    float acc[2][4];
#pragma unroll
    for (int i = 0; i < 2; i++)
#pragma unroll
        for (int j = 0; j < 4; j++) acc[i][j] = 0.0f;

    for (int k0 = 0; k0 < K; k0 += 32) {
        {
            int r = tid >> 3, kq = tid & 7;
            float4 v = *reinterpret_cast<const float4*>(&A[(size_t)(row0 + r) * K + k0 + kq * 4]);
            As[kq * 4 + 0][r] = v.x; As[kq * 4 + 1][r] = v.y;
            As[kq * 4 + 2][r] = v.z; As[kq * 4 + 3][r] = v.w;
        }
#pragma unroll
        for (int i = 0; i < 2; i++) {
            int idx = tid + i * 256;
            int r = idx >> 3, kq = idx & 7;
            float4 v = *reinterpret_cast<const float4*>(&Bbase[(size_t)(bn0 + r) * K + k0 + kq * 4]);
            Bs[kq * 4 + 0][r] = v.x; Bs[kq * 4 + 1][r] = v.y;
            Bs[kq * 4 + 2][r] = v.z; Bs[kq * 4 + 3][r] = v.w;
        }
        __syncthreads();

#pragma unroll
        for (int kk = 0; kk < 32; kk++) {
            float ar[2];
            ar[0] = As[kk][ty * 2 + 0];
            ar[1] = As[kk][ty * 2 + 1];
            float4 b4 = *reinterpret_cast<const float4*>(&Bs[kk][tx * 4]);
            acc[0][0] += ar[0] * b4.x; acc[0][1] += ar[0] * b4.y;
            acc[0][2] += ar[0] * b4.z; acc[0][3] += ar[0] * b4.w;
            acc[1][0] += ar[1] * b4.x; acc[1][1] += ar[1] * b4.y;
            acc[1][2] += ar[1] * b4.z; acc[1][3] += ar[1] * b4.w;
        }
        __syncthreads();
    }

#pragma unroll
    for (int i = 0; i < 2; i++) {
        float4 v = make_float4(acc[i][0], acc[i][1], acc[i][2], acc[i][3]);
        *reinterpret_cast<float4*>(&C[(size_t)(row0 + ty * 2 + i) * N + col0 + tx * 4]) = v;
    }
}

// -------------------- fused q-projection + M build + apply --------------------
// cp.async 3-stage pipeline, fp16 smem, 16B-granular swizzle, ldmatrix fragments.
// Stage layout: A region 128 rows x 4 units(16B), B region 64 rows x 4 units.
// Swizzle: logical unit u of row r placed at u ^ sw(r), sw(r) = (r&3) ^ ((r>>2)&1).

#define QBM 128
#define QBN 64
#define STGB 12288                          // bytes per stage
#define STGW 3072                           // words per stage
#define ABYTES 8192                         // A region bytes
#define AWORDS 2048
#define KBW  (3 * STGW)                     // kb word offset
#define VBW  (KBW + T_ * HD_)
#define SPKW (VBW + T_ * HD_)
#define SMEM_WORDS (SPKW + T_)
#define SMEM_BYTES (SMEM_WORDS * 4)         // 69888 B

__device__ __forceinline__ int swz(int r) { return (r & 3) ^ ((r >> 2) & 1); }

__device__ __forceinline__ void cp16(uint32_t dst, const void* src) {
    asm volatile("cp.async.ca.shared.global [%0], [%1], 16;" :: "r"(dst), "l"(src));
}
#define CP_COMMIT() asm volatile("cp.async.commit_group;")
template <int N> __device__ __forceinline__ void cp_wait() {
    asm volatile("cp.async.wait_group %0;" :: "n"(N));
}

__device__ __forceinline__ void ldsm4(uint32_t& r0, uint32_t& r1, uint32_t& r2, uint32_t& r3,
                                      uint32_t addr) {
    asm volatile("ldmatrix.sync.aligned.m8n8.x4.shared.b16 {%0,%1,%2,%3}, [%4];"
                 : "=r"(r0), "=r"(r1), "=r"(r2), "=r"(r3) : "r"(addr));
}

__device__ __forceinline__ void mma_f16(float c[4], uint32_t a0, uint32_t a1,
                                        uint32_t a2, uint32_t a3,
                                        uint32_t b0, uint32_t b1) {
    asm volatile(
        "mma.sync.aligned.m16n8k16.row.col.f32.f16.f16.f32 "
        "{%0,%1,%2,%3}, {%4,%5,%6,%7}, {%8,%9}, {%0,%1,%2,%3};"
        : "+f"(c[0]), "+f"(c[1]), "+f"(c[2]), "+f"(c[3])
        : "r"(a0), "r"(a1), "r"(a2), "r"(a3), "r"(b0), "r"(b1));
}

// phase-2 scalar word store into swizzled layout: word w (0..15) of row r
__device__ __forceinline__ void sw_store_w(uint32_t* region, int r, int w, uint32_t v) {
    region[r * 16 + ((((w >> 2) ^ swz(r)) << 2) | (w & 3))] = v;
}

// one BK=32 stage of mma via ldmatrix; offsets are byte offsets relative to stage base
__device__ __forceinline__ void mma_stage(uint32_t sbase, const uint32_t offA[2][2],
                                          const uint32_t offB[2][2], float acc[2][4][4]) {
#pragma unroll
    for (int ks = 0; ks < 2; ks++) {
        uint32_t a[2][4], bb[2][4];
#pragma unroll
        for (int mt = 0; mt < 2; mt++)
            ldsm4(a[mt][0], a[mt][1], a[mt][2], a[mt][3], sbase + offA[mt][ks]);
#pragma unroll
        for (int P = 0; P < 2; P++)
            ldsm4(bb[P][0], bb[P][1], bb[P][2], bb[P][3], sbase + offB[P][ks]);
#pragma unroll
        for (int mt = 0; mt < 2; mt++)
#pragma unroll
            for (int nt = 0; nt < 4; nt++) {
                const int P = nt >> 1, pp = nt & 1;
                mma_f16(acc[mt][nt], a[mt][0], a[mt][1], a[mt][2], a[mt][3],
                        bb[P][2 * pp], bb[P][2 * pp + 1]);
            }
    }
}

__global__ __launch_bounds__(256, 2)
void qgemm_fused_kernel(const float* __restrict__ tok, const int* __restrict__ spk,
                        float* __restrict__ out) {
    extern __shared__ uint32_t smem[];
    const uint32_t smem_s = (uint32_t)__cvta_generic_to_shared(smem);

    const int tid  = threadIdx.x;
    const int warp = tid >> 5;
    const int lane = tid & 31;
    const int gid  = lane >> 2;
    const int c4   = lane & 3;
    const int warp_m = warp & 3;
    const int warp_n = warp >> 2;

    const int hblk = blockIdx.x;
    const int bt   = blockIdx.y;
    const int b    = bt >> 6;
    const int tloc = bt & 63;
    const int row0 = bt * QBM;
    const int col0 = hblk * QBN;

    // ---- cp.async source/dest (relative byte offsets within stage) ----
    const int rA0 = tid >> 2,          uA0 = tid & 3;
    const int rA1 = (tid + 256) >> 2,  uA1 = tid & 3;   // idx+256: u unchanged, r += 64
    const int rB  = tid >> 2,          uB  = tid & 3;
    const __half* gA0 = g_tokh + (size_t)(row0 + rA0) * D_ + uA0 * 8;
    const __half* gA1 = g_tokh + (size_t)(row0 + rA1) * D_ + uA1 * 8;
    const __half* gB  = g_Wqh  + (size_t)(col0 + rB) * D_ + uB * 8;
    const uint32_t dA0 = rA0 * 64 + ((uA0 ^ swz(rA0)) << 4);
    const uint32_t dA1 = rA1 * 64 + ((uA1 ^ swz(rA1)) << 4);
    const uint32_t dB  = ABYTES + rB * 64 + ((uB ^ swz(rB)) << 4);

    // ---- ldmatrix lane offsets (relative byte offsets within stage) ----
    uint32_t offA[2][2], offB[2][2];
#pragma unroll
    for (int mt = 0; mt < 2; mt++)
#pragma unroll
        for (int ks = 0; ks < 2; ks++) {
            int r = warp_m * 32 + mt * 16 + (lane & 7) + ((lane >> 3) & 1) * 8;
            int u = 2 * ks + (lane >> 4);
            offA[mt][ks] = r * 64 + ((u ^ swz(r)) << 4);
        }
#pragma unroll
    for (int P = 0; P < 2; P++)
#pragma unroll
        for (int ks = 0; ks < 2; ks++) {
            int n = warp_n * 32 + P * 16 + (lane & 7) + ((lane >> 4) & 1) * 8;
            int u = 2 * ks + ((lane >> 3) & 1);
            offB[P][ks] = ABYTES + n * 64 + ((u ^ swz(n)) << 4);
        }

    float cacc[2][4][4];
#pragma unroll
    for (int mt = 0; mt < 2; mt++)
#pragma unroll
        for (int nt = 0; nt < 4; nt++)
#pragma unroll
            for (int i = 0; i < 4; i++) cacc[mt][nt][i] = 0.0f;

    // ---- prologue: stages 0,1 in flight ----
    {
        cp16(smem_s + 0 * STGB + dA0, gA0 + 0);
        cp16(smem_s + 0 * STGB + dA1, gA1 + 0);
        cp16(smem_s + 0 * STGB + dB,  gB  + 0);
        CP_COMMIT();
        cp16(smem_s + 1 * STGB + dA0, gA0 + 32);
        cp16(smem_s + 1 * STGB + dA1, gA1 + 32);
        cp16(smem_s + 1 * STGB + dB,  gB  + 32);
        CP_COMMIT();
    }

    // ---- main loop: 24 iterations, 3-stage pipeline, 1 barrier/iter ----
#pragma unroll
    for (int it = 0; it < 24; it++) {
        if (it == 23) cp_wait<0>(); else cp_wait<1>();
        __syncthreads();
        if (it + 2 < 24) {
            const uint32_t sb = smem_s + ((it + 2) % 3) * STGB;
            const int k = (it + 2) * 32;
            cp16(sb + dA0, gA0 + k);
            cp16(sb + dA1, gA1 + k);
            cp16(sb + dB,  gB  + k);
            CP_COMMIT();
        }
        mma_stage(smem_s + (it % 3) * STGB, offA, offB, cacc);
    }

    // ---------------- phase 2: build M in-block, then out = tok + q @ M ----------------
    float* kbs  = reinterpret_cast<float*>(smem + KBW);
    float* vbs  = reinterpret_cast<float*>(smem + VBW);
    int*   sspk = reinterpret_cast<int*>(smem + SPKW);

    // stage k,v for (b,h) into disjoint scratch (safe pre-sync)
    {
        const float* kvb = g_kvproj + (size_t)(b * T_) * (2 * D_);
#pragma unroll
        for (int i = 0; i < 4; i++) {
            int idx = tid + i * 256;
            int u = idx >> 4, dq = idx & 15;
            *reinterpret_cast<float4*>(&kbs[u * HD_ + dq * 4]) =
                *reinterpret_cast<const float4*>(&kvb[(size_t)u * (2 * D_) + hblk * HD_ + dq * 4]);
            *reinterpret_cast<float4*>(&vbs[u * HD_ + dq * 4]) =
                *reinterpret_cast<const float4*>(&kvb[(size_t)u * (2 * D_) + D_ + hblk * HD_ + dq * 4]);
        }
        if (tid < T_) sspk[tid] = spk[b * T_ + tid];
    }

    // write q (fp16) into A-areas of stages 0/1 (k-col c: stage = c>>5).
    // Safe without extra barrier: stages 0,1 were last read by mma(21),(22),
    // complete before barrier(23) for all threads; concurrent mma(23) reads stage 2 only.
    {
        uint32_t* Areg = smem + warp_n * STGW;
#pragma unroll
        for (int mt = 0; mt < 2; mt++) {
#pragma unroll
            for (int nt = 0; nt < 4; nt++) {
                int r = warp_m * 32 + mt * 16 + gid;
                int w = nt * 4 + c4;                 // word within 32-col stage
                sw_store_w(Areg, r,     w, pack_h2(cacc[mt][nt][0], cacc[mt][nt][1]));
                sw_store_w(Areg, r + 8, w, pack_h2(cacc[mt][nt][2], cacc[mt][nt][3]));
            }
        }
    }
    __syncthreads();   // kv/spk visible; q writes done

    // build M[d][e] (fp32, ascending u); store M^T (fp16) into B-areas of stages 0/1
    {
        const int dp = tid >> 3;            // d0 = 2dp, d1 = 2dp+1
        const int e0 = (tid & 7) * 8;
        const int d0 = dp * 2;
        const int myspk = sspk[tloc];
        float m0[8], m1[8];
#pragma unroll
        for (int j = 0; j < 8; j++) { m0[j] = 0.0f; m1[j] = 0.0f; }

        for (int u = 0; u <= tloc; u++) {
            if (sspk[u] != myspk) continue;
            float kd0 = kbs[u * HD_ + d0];
            float kd1 = kbs[u * HD_ + d0 + 1];
#pragma unroll
            for (int j4 = 0; j4 < 2; j4++) {
                float4 v4 = *reinterpret_cast<const float4*>(&vbs[u * HD_ + e0 + j4 * 4]);
                m0[j4 * 4 + 0] += kd0 * v4.x; m1[j4 * 4 + 0] += kd1 * v4.x;
                m0[j4 * 4 + 1] += kd0 * v4.y; m1[j4 * 4 + 1] += kd1 * v4.y;
                m0[j4 * 4 + 2] += kd0 * v4.z; m1[j4 * 4 + 2] += kd1 * v4.z;
                m0[j4 * 4 + 3] += kd0 * v4.w; m1[j4 * 4 + 3] += kd1 * v4.w;
            }
        }
        uint32_t* Breg = smem + (dp >> 4) * STGW + AWORDS;
#pragma unroll
        for (int j = 0; j < 8; j++) {
            sw_store_w(Breg, e0 + j, dp & 15, pack_h2(m0[j], m1[j]));
        }
    }
    __syncthreads();

    // apply: acc = q @ M over K=64 (stages 0,1)
#pragma unroll
    for (int mt = 0; mt < 2; mt++)
#pragma unroll
        for (int nt = 0; nt < 4; nt++)
#pragma unroll
            for (int i = 0; i < 4; i++) cacc[mt][nt][i] = 0.0f;

    mma_stage(smem_s + 0 * STGB, offA, offB, cacc);
    mma_stage(smem_s + 1 * STGB, offA, offB, cacc);

    // epilogue: out = tok + acc (exact fp32 residual)
#pragma unroll
    for (int mt = 0; mt < 2; mt++) {
#pragma unroll
        for (int nt = 0; nt < 4; nt++) {
            int row = row0 + warp_m * 32 + mt * 16 + gid;
            int col = col0 + warp_n * 32 + nt * 8 + c4 * 2;
            size_t a0 = (size_t)row * D_ + col;
            size_t a1 = (size_t)(row + 8) * D_ + col;
            float2 x0 = *reinterpret_cast<const float2*>(tok + a0);
            float2 x1 = *reinterpret_cast<const float2*>(tok + a1);
            *reinterpret_cast<float2*>(out + a0) =
                make_float2(cacc[mt][nt][0] + x0.x, cacc[mt][nt][1] + x0.y);
            *reinterpret_cast<float2*>(out + a1) =
                make_float2(cacc[mt][nt][2] + x1.x, cacc[mt][nt][3] + x1.y);
        }
    }
}

// -------------------- launch --------------------
extern "C" void kernel_launch(void* const* d_in, const int* in_sizes, int n_in,
                              void* d_out, int out_size) {
    const int*   spk = (const int*)d_in[1];
    const float* tok = (const float*)d_in[2];
    const float* edu = (const float*)d_in[3];
    const float* Wk  = (const float*)d_in[4];
    const float* Wv  = (const float*)d_in[5];
    const float* Wq  = (const float*)d_in[6];
    float* out = (float*)d_out;

    float* p_kvproj; cudaGetSymbolAddress((void**)&p_kvproj, g_kvproj);

    cudaFuncSetAttribute(qgemm_fused_kernel,
                         cudaFuncAttributeMaxDynamicSharedMemorySize, SMEM_BYTES);

    // 0) fp16 pre-convert of tok and Wq
    {
        const size_t total = (size_t)B_ * T_ * L_ * D_ + (size_t)D_ * D_;
        int blocks = (int)(total / (256 * 8));       // 12576, exact
        tofp16_kernel<<<blocks, 256>>>(tok, Wq);
    }

    // 1) kv projection (fp32)
    {
        dim3 grid((2 * D_) / 64, (B_ * T_) / 32);    // (24, 8)
        kvproj_kernel<<<grid, 256>>>(edu, Wk, Wv, p_kvproj);
    }

    // 2) fused q projection + M build + apply + residual
    {
        dim3 grid(H_, B_ * T_);                      // (12, 256)
        qgemm_fused_kernel<<<grid, 256, SMEM_BYTES>>>(tok, spk, out);
    }
}